// round 2
// baseline (speedup 1.0000x reference)
#include <cuda_runtime.h>
#include <cstdint>

#define Bt    1024
#define Tt    1000
#define HH    256
#define GBv   8
#define NBLK  128
#define NTHR  256
#define ICC   88          // W2/W3 rows cached in SMEM
// streamed rows: 256-88 = 168 = 21 chunks of 8

using u64 = unsigned long long;

__device__ float g_Wxz[16 * HH];        // W1[16:32] + W1[32:48], i-major
__device__ float g_cinit[Bt * HH];      // b1 + a @ (W1[0:16] - W1[16:32])

__device__ __forceinline__ u64 ffma2(u64 a, u64 b, u64 c) {
    u64 d; asm("fma.rn.f32x2 %0,%1,%2,%3;" : "=l"(d) : "l"(a), "l"(b), "l"(c)); return d;
}
__device__ __forceinline__ u64 pack2(float x, float y) {
    u64 d; asm("mov.b64 %0,{%1,%2};" : "=l"(d) : "f"(x), "f"(y)); return d;
}
__device__ __forceinline__ float2 unpack2(u64 a) {
    float2 f; asm("mov.b64 {%0,%1},%2;" : "=f"(f.x), "=f"(f.y) : "l"(a)); return f;
}
__device__ __forceinline__ float elu1(float v) { return v > 0.f ? v : (__expf(v) - 1.f); }

// ---------------- prep kernels ----------------
__global__ void prep_wxz(const float* __restrict__ W1) {
    int i = blockIdx.x, j = threadIdx.x;
    g_Wxz[i * HH + j] = W1[(16 + i) * HH + j] + W1[(32 + i) * HH + j];
}

__global__ void prep_cinit(const float* __restrict__ x, const float* __restrict__ z,
                           const float* __restrict__ W1, const float* __restrict__ b1) {
    int b = blockIdx.x, j = threadIdx.x;
    float c = b1[j];
#pragma unroll
    for (int i = 0; i < 16; i++) {
        float a = (i < 8) ? x[(size_t)b * Tt * 8 + i] : z[(size_t)b * Tt * 8 + (i - 8)];
        c += a * (W1[i * HH + j] - W1[(16 + i) * HH + j]);
    }
    g_cinit[b * HH + j] = c;
}

// ---------------- SMEM layout (floats) ----------------
#define OFF_W2  0                       // 88*256 = 22528
#define OFF_W3  22528                   // 22528
#define OFF_HA  45056                   // 2048
#define OFF_HB  47104                   // 2048
#define OFF_CI  49152                   // 2048
#define OFF_W4  51200                   // 2048
#define OFF_T   53248                   // 1024
#define OFF_INP 54272                   // 128
#define OFF_RED 54400                   // 256
#define OFF_ZJ  54656                   // 64
#define OFF_EVT 54720                   // 8
#define OFF_B4  54728                   // 8
#define SM_FLOATS 54736
#define SM_BYTES (SM_FLOATS * 4)        // 218944 B

// one 256->256 layer for this thread's (j0, j0+1) x 4 batches (hb = half*4)
__device__ __forceinline__ void biglayer(int j0, int hb,
                                         const float* __restrict__ hsrc,
                                         float* __restrict__ hdst,
                                         const float* __restrict__ wc,
                                         const float* __restrict__ Wg,
                                         u64 bd0, u64 bd1)
{
    u64 a00 = bd0, a01 = bd0, a10 = bd1, a11 = bd1;
    // phase 1: SMEM-cached rows i in [0, ICC)
#pragma unroll 4
    for (int i = 0; i < ICC; i++) {
        float2 w = *(const float2*)(wc + i * HH + j0);
        u64 wd0 = pack2(w.x, w.x), wd1 = pack2(w.y, w.y);
        ulonglong2 hv = *(const ulonglong2*)(hsrc + i * 8 + hb);
        a00 = ffma2(hv.x, wd0, a00); a01 = ffma2(hv.y, wd0, a01);
        a10 = ffma2(hv.x, wd1, a10); a11 = ffma2(hv.y, wd1, a11);
    }
    // phase 2: L2-streamed rows i in [ICC, 256), chunks of 8, double-buffered
    float2 buf[2][8];
    const float* gp = Wg + ICC * HH + j0;
#pragma unroll
    for (int q = 0; q < 8; q++) buf[0][q] = __ldg((const float2*)(gp + q * HH));
#pragma unroll 1
    for (int c = 0; c < 21; c++) {
        float2* cur = buf[c & 1];
        float2* nxt = buf[(c + 1) & 1];
        if (c < 20) {
            const float* gn = gp + (size_t)(c + 1) * 8 * HH;
#pragma unroll
            for (int q = 0; q < 8; q++) nxt[q] = __ldg((const float2*)(gn + q * HH));
        }
        int ib = ICC + c * 8;
#pragma unroll
        for (int q = 0; q < 8; q++) {
            u64 wd0 = pack2(cur[q].x, cur[q].x), wd1 = pack2(cur[q].y, cur[q].y);
            ulonglong2 hv = *(const ulonglong2*)(hsrc + (ib + q) * 8 + hb);
            a00 = ffma2(hv.x, wd0, a00); a01 = ffma2(hv.y, wd0, a01);
            a10 = ffma2(hv.x, wd1, a10); a11 = ffma2(hv.y, wd1, a11);
        }
    }
    float2 f00 = unpack2(a00), f01 = unpack2(a01), f10 = unpack2(a10), f11 = unpack2(a11);
    float4 o0 = make_float4(elu1(f00.x), elu1(f00.y), elu1(f01.x), elu1(f01.y));
    float4 o1 = make_float4(elu1(f10.x), elu1(f10.y), elu1(f11.x), elu1(f11.y));
    *(float4*)(hdst + j0 * 8 + hb) = o0;
    *(float4*)(hdst + (j0 + 1) * 8 + hb) = o1;
}

__global__ __launch_bounds__(NTHR, 1)
void ode_main(const float* __restrict__ t, const float* __restrict__ x,
              const float* __restrict__ z, const float* __restrict__ event_t,
              const float* __restrict__ z_jump,
              const float* __restrict__ W2, const float* __restrict__ b2,
              const float* __restrict__ W3, const float* __restrict__ b3,
              const float* __restrict__ W4, const float* __restrict__ b4,
              float* __restrict__ out)
{
    extern __shared__ float sm[];
    float* w2c = sm + OFF_W2;
    float* w3c = sm + OFF_W3;
    float* hA  = sm + OFF_HA;
    float* hB  = sm + OFF_HB;
    float* ci  = sm + OFF_CI;
    float* w4c = sm + OFF_W4;
    float* ts  = sm + OFF_T;
    float* inp = sm + OFF_INP;
    float* red = sm + OFF_RED;
    float* zjs = sm + OFF_ZJ;
    float* evts= sm + OFF_EVT;
    float* b4s = sm + OFF_B4;

    const int tid = threadIdx.x;
    const int b0  = blockIdx.x * GBv;

    // fill SMEM caches (coalesced)
    for (int idx = tid; idx < ICC * HH; idx += NTHR) { w2c[idx] = W2[idx]; w3c[idx] = W3[idx]; }
    for (int idx = tid; idx < HH * 8; idx += NTHR) w4c[idx] = W4[idx];
    for (int i = tid; i < Tt; i += NTHR) ts[i] = t[i];
    for (int idx = tid; idx < HH * 8; idx += NTHR) {
        int j = idx >> 3, g = idx & 7;
        ci[idx] = g_cinit[(size_t)(b0 + g) * HH + j];
    }
    if (tid < 8) { evts[tid] = event_t[b0 + tid]; b4s[tid] = b4[tid]; }
    if (tid < 64) { int g = tid >> 3, i = tid & 7; zjs[tid] = z_jump[(b0 + g) * 8 + i]; }

    // lane decomposition: thread owns j-pair (j0, j0+1) x 4 batches (hb..hb+3)
    const int lane = tid & 31;
    const int warp = tid >> 5;
    const int half = lane >> 4;
    const int j0 = warp * 32 + (lane & 15) * 2;
    const int hb = half * 4;

    // per-thread resident weights
    float2 wxz[16];
#pragma unroll
    for (int i = 0; i < 16; i++) wxz[i] = *(const float2*)&g_Wxz[i * HH + j0];
    const u64 bd2_0 = pack2(b2[j0], b2[j0]), bd2_1 = pack2(b2[j0 + 1], b2[j0 + 1]);
    const u64 bd3_0 = pack2(b3[j0], b3[j0]), bd3_1 = pack2(b3[j0 + 1], b3[j0 + 1]);

    // layer-4 mapping
    const int c4 = tid >> 6, r4 = tid & 63, k4 = r4 & 7, g4 = r4 >> 3;

    // z prefetch state (threads 64..127 own one (g, zdim) slot)
    float zreg = 0.f;
    size_t zbase = 0;
    if (tid >= 64 && tid < 128) {
        int r = tid - 64, g = r >> 3, i = r & 7;
        zbase = (size_t)(b0 + g) * Tt * 8 + i;
    }

    // step-0 input + output row 0
    if (tid < 64) {
        int k = tid & 7, g = tid >> 3;
        float xv = x[(size_t)(b0 + g) * Tt * 8 + k];
        inp[k * 8 + g] = xv;
        out[(size_t)(b0 + g) * Tt * 8 + k] = xv;
    }
    __syncthreads();
    if (tid >= 64 && tid < 128) {
        int r = tid - 64, g = r >> 3;
        float z0 = z[zbase];
        inp[(8 + (r & 7)) * 8 + g] = (ts[0] >= evts[g]) ? zjs[r] : z0;
        zreg = z[zbase + 8];     // z for step 1
    }
    __syncthreads();

    for (int s = 0; s < Tt - 1; s++) {
        const float t1 = ts[s + 1];
        const float dt = t1 - ts[s];

        // ---- layer 1 (K=16, folded) ----
        {
            ulonglong2 c0 = *(const ulonglong2*)(ci + j0 * 8 + hb);
            ulonglong2 c1 = *(const ulonglong2*)(ci + (j0 + 1) * 8 + hb);
            u64 a00 = c0.x, a01 = c0.y, a10 = c1.x, a11 = c1.y;
#pragma unroll
            for (int i = 0; i < 16; i++) {
                u64 wd0 = pack2(wxz[i].x, wxz[i].x), wd1 = pack2(wxz[i].y, wxz[i].y);
                ulonglong2 hv = *(const ulonglong2*)(inp + i * 8 + hb);
                a00 = ffma2(hv.x, wd0, a00); a01 = ffma2(hv.y, wd0, a01);
                a10 = ffma2(hv.x, wd1, a10); a11 = ffma2(hv.y, wd1, a11);
            }
            float2 f00 = unpack2(a00), f01 = unpack2(a01), f10 = unpack2(a10), f11 = unpack2(a11);
            float4 o0 = make_float4(elu1(f00.x), elu1(f00.y), elu1(f01.x), elu1(f01.y));
            float4 o1 = make_float4(elu1(f10.x), elu1(f10.y), elu1(f11.x), elu1(f11.y));
            *(float4*)(hA + j0 * 8 + hb) = o0;
            *(float4*)(hA + (j0 + 1) * 8 + hb) = o1;
        }
        __syncthreads();

        // prefetch z for step s+2 (hidden under layer 2/3 compute)
        float znext = 0.f;
        if (tid >= 64 && tid < 128 && s + 2 < Tt) znext = z[zbase + (size_t)(s + 2) * 8];

        // ---- layers 2, 3 ----
        biglayer(j0, hb, hA, hB, w2c, W2, bd2_0, bd2_1);
        __syncthreads();
        biglayer(j0, hb, hB, hA, w3c, W3, bd3_0, bd3_1);
        __syncthreads();

        // ---- layer 4 partials: thread (c4,k4,g4) sums 64 i's ----
        {
            float p = 0.f;
            int base = c4 * 64;
#pragma unroll 8
            for (int i = 0; i < 64; i++)
                p += hA[(base + i) * 8 + g4] * w4c[(base + i) * 8 + k4];
            red[tid] = p;
        }
        __syncthreads();

        // ---- epilogue: Euler update + next-step input build ----
        if (tid < 64) {
            int k = tid & 7, g = tid >> 3;
            float o = b4s[k] + red[tid] + red[tid + 64] + red[tid + 128] + red[tid + 192];
            float xn = inp[k * 8 + g] + dt * o;
            inp[k * 8 + g] = xn;
            out[(size_t)(b0 + g) * Tt * 8 + (size_t)(s + 1) * 8 + k] = xn;
        } else if (tid < 128) {
            int r = tid - 64, g = r >> 3;
            inp[(8 + (r & 7)) * 8 + g] = (t1 >= evts[g]) ? zjs[r] : zreg;
            zreg = znext;
        }
        __syncthreads();
    }
}

extern "C" void kernel_launch(void* const* d_in, const int* in_sizes, int n_in,
                              void* d_out, int out_size) {
    const float* t       = (const float*)d_in[0];
    const float* x       = (const float*)d_in[1];
    const float* z       = (const float*)d_in[2];
    const float* event_t = (const float*)d_in[3];
    const float* z_jump  = (const float*)d_in[4];
    const float* W1      = (const float*)d_in[5];
    const float* b1      = (const float*)d_in[6];
    const float* W2      = (const float*)d_in[7];
    const float* b2      = (const float*)d_in[8];
    const float* W3      = (const float*)d_in[9];
    const float* b3      = (const float*)d_in[10];
    const float* W4      = (const float*)d_in[11];
    const float* b4      = (const float*)d_in[12];
    float* out = (float*)d_out;

    cudaFuncSetAttribute(ode_main, cudaFuncAttributeMaxDynamicSharedMemorySize, SM_BYTES);

    prep_wxz<<<16, HH>>>(W1);
    prep_cinit<<<Bt, HH>>>(x, z, W1, b1);
    ode_main<<<NBLK, NTHR, SM_BYTES>>>(t, x, z, event_t, z_jump,
                                       W2, b2, W3, b3, W4, b4, out);
}

// round 3
// speedup vs baseline: 1.2808x; 1.2808x over previous
#include <cuda_runtime.h>
#include <cstdint>

#define Bt    1024
#define Tt    1000
#define HH    256
#define NBLK  128
#define NTHR  256
#define ICC   64              // W2/W3 rows resident in SMEM
#define CHROWS 12             // rows per streamed chunk
#define NCH   16              // chunks per layer: (256-64)/12
#define NSTG  3               // pipeline stages

using u64 = unsigned long long;

__device__ float g_Wxz[16 * HH];      // W1[16:32]+W1[32:48], i-major
__device__ float g_cinit[Bt * HH];    // b1 + a @ (W1[0:16]-W1[16:32])

__device__ __forceinline__ u64 ffma2(u64 a, u64 b, u64 c) {
    u64 d; asm("fma.rn.f32x2 %0,%1,%2,%3;" : "=l"(d) : "l"(a), "l"(b), "l"(c)); return d;
}
__device__ __forceinline__ u64 pack2(float x, float y) {
    u64 d; asm("mov.b64 %0,{%1,%2};" : "=l"(d) : "f"(x), "f"(y)); return d;
}
__device__ __forceinline__ float2 unpack2(u64 a) {
    float2 f; asm("mov.b64 {%0,%1},%2;" : "=f"(f.x), "=f"(f.y) : "l"(a)); return f;
}
__device__ __forceinline__ float elu1(float v) { return v > 0.f ? v : (__expf(v) - 1.f); }

// ---------------- prep kernels ----------------
__global__ void prep_wxz(const float* __restrict__ W1) {
    int i = blockIdx.x, j = threadIdx.x;
    g_Wxz[i * HH + j] = W1[(16 + i) * HH + j] + W1[(32 + i) * HH + j];
}
__global__ void prep_cinit(const float* __restrict__ x, const float* __restrict__ z,
                           const float* __restrict__ W1, const float* __restrict__ b1) {
    int b = blockIdx.x, j = threadIdx.x;
    float c = b1[j];
#pragma unroll
    for (int i = 0; i < 16; i++) {
        float a = (i < 8) ? x[(size_t)b * Tt * 8 + i] : z[(size_t)b * Tt * 8 + (i - 8)];
        c += a * (W1[i * HH + j] - W1[(16 + i) * HH + j]);
    }
    g_cinit[b * HH + j] = c;
}

// ---------------- SMEM layout (float offsets) ----------------
#define OFF_W2   0                           // 16384
#define OFF_W3   16384                       // 16384
#define OFF_STR  32768                       // 3*12*256 = 9216
#define OFF_HA   41984                       // 256*16 = 4096 (dup)
#define OFF_HB   46080                       // 4096 (dup)
#define OFF_H3   50176                       // 8*260 = 2080
#define OFF_W4   52256                       // 8*260 = 2080
#define OFF_TS   54336                       // 1024
#define OFF_INP  55360                       // 16*16 = 256 (dup)
#define OFF_RED  55616                       // 256
#define OFF_ZJ   55872                       // 64
#define OFF_EVT  55936                       // 8
#define OFF_B4   55944                       // 8
#define SM_FLOATS 55952
#define SM_BYTES  (SM_FLOATS * 4)            // 223808 B

#define STG_FLOATS (CHROWS * HH)             // 3072

// accumulate n rows: acc[g'] (j-pair) += w[i][j0..j1] * hdup[i][g]
__device__ __forceinline__ void accum_rows(const float* __restrict__ wrows,
                                           const float* __restrict__ hdup,
                                           int i0, int n, int j0, int gq8, u64* acc) {
#pragma unroll 4
    for (int q = 0; q < n; q++) {
        u64 wd = *(const u64*)(wrows + q * HH + j0);
        const float* hr = hdup + (i0 + q) * 16 + gq8;
        ulonglong2 h01 = *(const ulonglong2*)(hr);
        ulonglong2 h23 = *(const ulonglong2*)(hr + 4);
        acc[0] = ffma2(h01.x, wd, acc[0]);
        acc[1] = ffma2(h01.y, wd, acc[1]);
        acc[2] = ffma2(h23.x, wd, acc[2]);
        acc[3] = ffma2(h23.y, wd, acc[3]);
    }
}

__device__ __forceinline__ void issue_chunk(int k, unsigned str_u32,
                                            const float* __restrict__ W2,
                                            const float* __restrict__ W3, int tid) {
    if (k >= 2 * NCH) return;
    const char* src = (const char*)((k < NCH ? W2 : W3) + (ICC + (k & (NCH - 1)) * CHROWS) * HH);
    unsigned dst = str_u32 + (unsigned)(k % NSTG) * (STG_FLOATS * 4);
#pragma unroll
    for (int r = 0; r < 3; r++) {
        unsigned off = (unsigned)(tid + r * NTHR) * 16;
        asm volatile("cp.async.cg.shared.global [%0], [%1], 16;" :: "r"(dst + off), "l"(src + off));
    }
    asm volatile("cp.async.commit_group;");
}

__global__ __launch_bounds__(NTHR, 1)
void ode_main(const float* __restrict__ t, const float* __restrict__ x,
              const float* __restrict__ z, const float* __restrict__ event_t,
              const float* __restrict__ z_jump,
              const float* __restrict__ W2, const float* __restrict__ b2,
              const float* __restrict__ W3, const float* __restrict__ b3,
              const float* __restrict__ W4, const float* __restrict__ b4,
              float* __restrict__ out)
{
    extern __shared__ float sm[];
    float* w2c  = sm + OFF_W2;
    float* w3c  = sm + OFF_W3;
    float* strb = sm + OFF_STR;
    float* hA   = sm + OFF_HA;
    float* hB   = sm + OFF_HB;
    float* h3p  = sm + OFF_H3;
    float* w4t  = sm + OFF_W4;
    float* ts   = sm + OFF_TS;
    float* inp  = sm + OFF_INP;
    float* red  = sm + OFF_RED;
    float* zjs  = sm + OFF_ZJ;
    float* evts = sm + OFF_EVT;
    float* b4s  = sm + OFF_B4;

    const int tid = threadIdx.x;
    const int b0  = blockIdx.x * 8;
    const unsigned str_u32 = (unsigned)__cvta_generic_to_shared(strb);

    // ---- init SMEM caches ----
    for (int idx = tid; idx < ICC * HH; idx += NTHR) { w2c[idx] = W2[idx]; w3c[idx] = W3[idx]; }
    for (int idx = tid; idx < 8 * HH; idx += NTHR) {
        int k = idx >> 8, i = idx & 255;
        w4t[k * 260 + i] = W4[i * 8 + k];
    }
    for (int i = tid; i < Tt; i += NTHR) ts[i] = t[i];
    if (tid < 8) { evts[tid] = event_t[b0 + tid]; b4s[tid] = b4[tid]; }
    if (tid < 64) { int g = tid >> 3, i = tid & 7; zjs[tid] = z_jump[(b0 + g) * 8 + i]; }

    // ---- lane decomposition ----
    const int lane = tid & 31, warp = tid >> 5;
    const int j0  = warp * 32 + (lane & 15) * 2;
    const int gq  = lane >> 4;            // 0/1 -> batches gq*4..gq*4+3
    const int gq8 = gq * 8;

    // per-thread resident weights / constants
    u64 wxz[16];
#pragma unroll
    for (int i = 0; i < 16; i++) wxz[i] = *(const u64*)&g_Wxz[i * HH + j0];
    u64 cig[4];
#pragma unroll
    for (int gp = 0; gp < 4; gp++) {
        int g = gq * 4 + gp;
        cig[gp] = *(const u64*)&g_cinit[(size_t)(b0 + g) * HH + j0];
    }
    const u64 bd2 = *(const u64*)&b2[j0];
    const u64 bd3 = *(const u64*)&b3[j0];

    // layer-4 mapping
    const int c4 = tid >> 6, r4 = tid & 63, k4 = r4 & 7, g4 = r4 >> 3;

    // z prefetch state (threads 64..127 own one (g, zdim) slot)
    float zreg = 0.f; size_t zbase = 0;
    if (tid >= 64 && tid < 128) {
        int r = tid - 64, g = r >> 3, i = r & 7;
        zbase = (size_t)(b0 + g) * Tt * 8 + i;
    }

    // ---- step-0 input (dup layout) + output row 0 ----
    if (tid < 64) {
        int k = tid & 7, g = tid >> 3;
        float xv = x[(size_t)(b0 + g) * Tt * 8 + k];
        inp[k * 16 + g * 2] = xv; inp[k * 16 + g * 2 + 1] = xv;
        out[(size_t)(b0 + g) * Tt * 8 + k] = xv;
    }
    __syncthreads();
    if (tid >= 64 && tid < 128) {
        int r = tid - 64, g = r >> 3, zi = r & 7;
        float z0 = z[zbase];
        float v = (ts[0] >= evts[g]) ? zjs[r] : z0;
        inp[(8 + zi) * 16 + g * 2] = v; inp[(8 + zi) * 16 + g * 2 + 1] = v;
        zreg = z[zbase + 8];
    }
    __syncthreads();

    for (int s = 0; s < Tt - 1; s++) {
        const float t1 = ts[s + 1];
        const float dt = t1 - ts[s];

        // stream prologue: chunks 0,1 in flight during layer 1
        issue_chunk(0, str_u32, W2, W3, tid);
        issue_chunk(1, str_u32, W2, W3, tid);

        // ---- layer 1 (K=16, folded) ----
        {
            u64 acc[4] = { cig[0], cig[1], cig[2], cig[3] };
#pragma unroll
            for (int i = 0; i < 16; i++) {
                const float* hr = inp + i * 16 + gq8;
                ulonglong2 h01 = *(const ulonglong2*)(hr);
                ulonglong2 h23 = *(const ulonglong2*)(hr + 4);
                acc[0] = ffma2(h01.x, wxz[i], acc[0]);
                acc[1] = ffma2(h01.y, wxz[i], acc[1]);
                acc[2] = ffma2(h23.x, wxz[i], acc[2]);
                acc[3] = ffma2(h23.y, wxz[i], acc[3]);
            }
#pragma unroll
            for (int gp = 0; gp < 4; gp++) {
                float2 v = unpack2(acc[gp]);
                v.x = elu1(v.x); v.y = elu1(v.y);
                int g = gq * 4 + gp;
                *(u64*)(hA + j0 * 16 + g * 2)       = pack2(v.x, v.x);
                *(u64*)(hA + (j0 + 1) * 16 + g * 2) = pack2(v.y, v.y);
            }
        }
        __syncthreads();

        // z prefetch for step s+2 (lands during layer 2/3)
        float znext = 0.f;
        if (tid >= 64 && tid < 128 && s + 2 < Tt) znext = z[zbase + (size_t)(s + 2) * 8];

        // ---- layer 2: cached rows + streamed chunks k=0..15 ----
        {
            u64 acc[4] = { bd2, bd2, bd2, bd2 };
            accum_rows(w2c, hA, 0, ICC, j0, gq8, acc);
#pragma unroll 1
            for (int c = 0; c < NCH; c++) {
                asm volatile("cp.async.wait_group 1;" ::: "memory");
                __syncthreads();
                issue_chunk(c + 2, str_u32, W2, W3, tid);
                accum_rows(strb + (c % NSTG) * STG_FLOATS, hA, ICC + c * CHROWS, CHROWS, j0, gq8, acc);
            }
#pragma unroll
            for (int gp = 0; gp < 4; gp++) {
                float2 v = unpack2(acc[gp]);
                v.x = elu1(v.x); v.y = elu1(v.y);
                int g = gq * 4 + gp;
                *(u64*)(hB + j0 * 16 + g * 2)       = pack2(v.x, v.x);
                *(u64*)(hB + (j0 + 1) * 16 + g * 2) = pack2(v.y, v.y);
            }
        }
        __syncthreads();

        // ---- layer 3: cached rows + streamed chunks k=16..31 ----
        {
            u64 acc[4] = { bd3, bd3, bd3, bd3 };
            accum_rows(w3c, hB, 0, ICC, j0, gq8, acc);
#pragma unroll 1
            for (int c = 0; c < NCH; c++) {
                const int k = NCH + c;
                if (k == 2 * NCH - 1) asm volatile("cp.async.wait_group 0;" ::: "memory");
                else                  asm volatile("cp.async.wait_group 1;" ::: "memory");
                __syncthreads();
                issue_chunk(k + 2, str_u32, W2, W3, tid);
                accum_rows(strb + (k % NSTG) * STG_FLOATS, hB, ICC + c * CHROWS, CHROWS, j0, gq8, acc);
            }
#pragma unroll
            for (int gp = 0; gp < 4; gp++) {
                float2 v = unpack2(acc[gp]);
                v.x = elu1(v.x); v.y = elu1(v.y);
                int g = gq * 4 + gp;
                *(float2*)(h3p + g * 260 + j0) = make_float2(v.x, v.y);
            }
        }
        __syncthreads();

        // ---- layer 4 partials (vectorized, padded layouts) ----
        {
            float p = 0.f;
            const int base = c4 * 64;
            const float* hp = h3p + g4 * 260 + base;
            const float* wp = w4t + k4 * 260 + base;
#pragma unroll
            for (int it = 0; it < 16; it++) {
                float4 hv = *(const float4*)(hp + it * 4);
                float4 wv = *(const float4*)(wp + it * 4);
                p = fmaf(hv.x, wv.x, p); p = fmaf(hv.y, wv.y, p);
                p = fmaf(hv.z, wv.z, p); p = fmaf(hv.w, wv.w, p);
            }
            red[tid] = p;
        }
        __syncthreads();

        // ---- epilogue: Euler update + next-step input ----
        if (tid < 64) {
            int k = tid & 7, g = tid >> 3;
            float o = b4s[k] + red[tid] + red[tid + 64] + red[tid + 128] + red[tid + 192];
            float xn = inp[k * 16 + g * 2] + dt * o;
            inp[k * 16 + g * 2] = xn; inp[k * 16 + g * 2 + 1] = xn;
            out[(size_t)(b0 + g) * Tt * 8 + (size_t)(s + 1) * 8 + k] = xn;
        } else if (tid < 128) {
            int r = tid - 64, g = r >> 3, zi = r & 7;
            float v = (t1 >= evts[g]) ? zjs[r] : zreg;
            inp[(8 + zi) * 16 + g * 2] = v; inp[(8 + zi) * 16 + g * 2 + 1] = v;
            zreg = znext;
        }
        __syncthreads();
    }
}

extern "C" void kernel_launch(void* const* d_in, const int* in_sizes, int n_in,
                              void* d_out, int out_size) {
    const float* t       = (const float*)d_in[0];
    const float* x       = (const float*)d_in[1];
    const float* z       = (const float*)d_in[2];
    const float* event_t = (const float*)d_in[3];
    const float* z_jump  = (const float*)d_in[4];
    const float* W1      = (const float*)d_in[5];
    const float* b1      = (const float*)d_in[6];
    const float* W2      = (const float*)d_in[7];
    const float* b2      = (const float*)d_in[8];
    const float* W3      = (const float*)d_in[9];
    const float* b3      = (const float*)d_in[10];
    const float* W4      = (const float*)d_in[11];
    const float* b4      = (const float*)d_in[12];
    float* out = (float*)d_out;

    cudaFuncSetAttribute(ode_main, cudaFuncAttributeMaxDynamicSharedMemorySize, SM_BYTES);

    prep_wxz<<<16, HH>>>(W1);
    prep_cinit<<<Bt, HH>>>(x, z, W1, b1);
    ode_main<<<NBLK, NTHR, SM_BYTES>>>(t, x, z, event_t, z_jump,
                                       W2, b2, W3, b3, W4, b4, out);
}

// round 4
// speedup vs baseline: 1.3579x; 1.0602x over previous
#include <cuda_runtime.h>
#include <cstdint>

#define Bt    1024
#define Tt    1000
#define HH    256
#define NBLK  128
#define NTHR  256
#define ICC   48              // W2/W3 rows resident in SMEM
#define CHROWS 16             // rows per streamed chunk
#define NCH   13              // chunks per layer: (256-48)/16
#define NKTOT (2*NCH)         // 26
#define NSTG  4               // pipeline stages

using u64 = unsigned long long;

__device__ __forceinline__ u64 ffma2(u64 a, u64 b, u64 c) {
    u64 d; asm("fma.rn.f32x2 %0,%1,%2,%3;" : "=l"(d) : "l"(a), "l"(b), "l"(c)); return d;
}
__device__ __forceinline__ u64 pack2(float x, float y) {
    u64 d; asm("mov.b64 %0,{%1,%2};" : "=l"(d) : "f"(x), "f"(y)); return d;
}
__device__ __forceinline__ float2 unpack2(u64 a) {
    float2 f; asm("mov.b64 {%0,%1},%2;" : "=f"(f.x), "=f"(f.y) : "l"(a)); return f;
}
__device__ __forceinline__ float elu1(float v) { return v > 0.f ? v : (__expf(v) - 1.f); }

// ---------------- SMEM layout (float offsets) ----------------
#define OFF_W2   0                      // 48*256 = 12288
#define OFF_W3   12288                  // 12288
#define OFF_STR  24576                  // 4*16*256 = 16384
#define OFF_HA   40960                  // 256*16 = 4096 (dup)
#define OFF_HB   45056                  // 4096
#define OFF_H3   49152                  // 8*260 = 2080
#define OFF_W4   51232                  // 8*260 = 2080
#define OFF_INP  53312                  // 16*16 = 256 (dup)
#define OFF_RED  53568                  // 256 (also scratch araw 128)
#define OFF_ZJ   53824                  // 64
#define OFF_EVT  53888                  // 8
#define OFF_B4   53896                  // 8
#define OFF_TSH  53904                  // 2
#define SM_FLOATS 53908
#define SM_BYTES  (SM_FLOATS * 4)       // 215632 B

#define STG_FLOATS (CHROWS * HH)        // 4096

// accumulate n rows: acc[g'] (j-pair) += w[i][j0:j0+2] * hdup[i][g]
__device__ __forceinline__ void accum_rows(const float* __restrict__ wrows,
                                           const float* __restrict__ hdup,
                                           int i0, int n, int j0, int gq8, u64* acc) {
#pragma unroll 8
    for (int q = 0; q < n; q++) {
        u64 wd = *(const u64*)(wrows + q * HH + j0);
        const float* hr = hdup + (i0 + q) * 16 + gq8;
        ulonglong2 h01 = *(const ulonglong2*)(hr);
        ulonglong2 h23 = *(const ulonglong2*)(hr + 4);
        acc[0] = ffma2(h01.x, wd, acc[0]);
        acc[1] = ffma2(h01.y, wd, acc[1]);
        acc[2] = ffma2(h23.x, wd, acc[2]);
        acc[3] = ffma2(h23.y, wd, acc[3]);
    }
}

__device__ __forceinline__ void issue_chunk(int k, unsigned str_u32,
                                            const float* __restrict__ W2,
                                            const float* __restrict__ W3, int tid) {
    if (k >= NKTOT) return;
    const int kl = (k < NCH) ? k : (k - NCH);
    const char* src = (const char*)((k < NCH ? W2 : W3) + (ICC + kl * CHROWS) * HH);
    unsigned dst = str_u32 + (unsigned)(k % NSTG) * (STG_FLOATS * 4);
#pragma unroll
    for (int r = 0; r < 4; r++) {
        unsigned off = (unsigned)(tid + r * NTHR) * 16;
        asm volatile("cp.async.cg.shared.global [%0], [%1], 16;" :: "r"(dst + off), "l"(src + off));
    }
    asm volatile("cp.async.commit_group;");
}

__global__ __launch_bounds__(NTHR, 1)
void ode_main(const float* __restrict__ t, const float* __restrict__ x,
              const float* __restrict__ z, const float* __restrict__ event_t,
              const float* __restrict__ z_jump,
              const float* __restrict__ W1, const float* __restrict__ b1,
              const float* __restrict__ W2, const float* __restrict__ b2,
              const float* __restrict__ W3, const float* __restrict__ b3,
              const float* __restrict__ W4, const float* __restrict__ b4,
              float* __restrict__ out)
{
    extern __shared__ float sm[];
    float* w2c  = sm + OFF_W2;
    float* w3c  = sm + OFF_W3;
    float* strb = sm + OFF_STR;
    float* hA   = sm + OFF_HA;
    float* hB   = sm + OFF_HB;
    float* h3p  = sm + OFF_H3;
    float* w4t  = sm + OFF_W4;
    float* inp  = sm + OFF_INP;
    float* red  = sm + OFF_RED;   // also araw scratch during init
    float* zjs  = sm + OFF_ZJ;
    float* evts = sm + OFF_EVT;
    float* b4s  = sm + OFF_B4;
    float* tsh  = sm + OFF_TSH;

    const int tid = threadIdx.x;
    const int b0  = blockIdx.x * 8;
    const unsigned str_u32 = (unsigned)__cvta_generic_to_shared(strb);

    // ---- lane decomposition ----
    const int lane = tid & 31, warp = tid >> 5;
    const int j0  = warp * 32 + (lane & 15) * 2;
    const int gq  = lane >> 4;
    const int gq8 = gq * 8;

    // ---- init phase A: SMEM caches + raw inputs ----
    for (int idx = tid; idx < ICC * HH; idx += NTHR) { w2c[idx] = W2[idx]; w3c[idx] = W3[idx]; }
    for (int idx = tid; idx < 8 * HH; idx += NTHR) {
        int k = idx >> 8, i = idx & 255;
        w4t[k * 260 + i] = W4[i * 8 + k];
    }
    if (tid < 8) { evts[tid] = event_t[b0 + tid]; b4s[tid] = b4[tid]; }
    if (tid < 64) { int g = tid >> 3, i = tid & 7; zjs[tid] = z_jump[(b0 + g) * 8 + i]; }
    if (tid == 0) { tsh[0] = t[0]; tsh[1] = t[1]; }

    float zreg = 0.f; size_t zbase = 0;
    if (tid >= 64 && tid < 128) {
        int r = tid - 64, g = r >> 3, i = r & 7;
        zbase = (size_t)(b0 + g) * Tt * 8 + i;
    }
    float treg = 0.f;
    if (tid == 192) treg = t[2];

    if (tid < 64) {                 // x0: araw, inp (dup), out row 0
        int k = tid & 7, g = tid >> 3;
        float xv = x[(size_t)(b0 + g) * Tt * 8 + k];
        red[k * 8 + g] = xv;
        inp[k * 16 + g * 2] = xv; inp[k * 16 + g * 2 + 1] = xv;
        out[(size_t)(b0 + g) * Tt * 8 + k] = xv;
    } else if (tid < 128) {         // z0 raw into araw; prefetch z1
        int r = tid - 64, g = r >> 3, zi = r & 7;
        float z0 = z[zbase];
        red[(8 + zi) * 8 + g] = z0;
        zreg = z[zbase + 8];
    }
    __syncthreads();

    // ---- init phase B: z_eff for step 0; per-thread wxz/cinit ----
    if (tid >= 64 && tid < 128) {
        int r = tid - 64, g = r >> 3, zi = r & 7;
        float v = (tsh[0] >= evts[g]) ? zjs[r] : red[(8 + zi) * 8 + g];
        inp[(8 + zi) * 16 + g * 2] = v; inp[(8 + zi) * 16 + g * 2 + 1] = v;
    }

    u64 wxz[16];
    u64 cig[4];
    {
        float c0 = b1[j0], c1 = b1[j0 + 1];
        float ca[4][2];
#pragma unroll
        for (int gp = 0; gp < 4; gp++) { ca[gp][0] = c0; ca[gp][1] = c1; }
#pragma unroll
        for (int i = 0; i < 16; i++) {
            float2 wa = *(const float2*)&W1[i * HH + j0];
            float2 wb = *(const float2*)&W1[(16 + i) * HH + j0];
            float2 wc = *(const float2*)&W1[(32 + i) * HH + j0];
            wxz[i] = pack2(wb.x + wc.x, wb.y + wc.y);
            float dx = wa.x - wb.x, dy = wa.y - wb.y;
#pragma unroll
            for (int gp = 0; gp < 4; gp++) {
                float a = red[i * 8 + gq * 4 + gp];
                ca[gp][0] = fmaf(a, dx, ca[gp][0]);
                ca[gp][1] = fmaf(a, dy, ca[gp][1]);
            }
        }
#pragma unroll
        for (int gp = 0; gp < 4; gp++) cig[gp] = pack2(ca[gp][0], ca[gp][1]);
    }
    const u64 bd2 = *(const u64*)&b2[j0];
    const u64 bd3 = *(const u64*)&b3[j0];

    const int c4 = tid >> 6, r4 = tid & 63, k4 = r4 & 7, g4 = r4 >> 3;
    __syncthreads();

    for (int s = 0; s < Tt - 1; s++) {
        const float t0 = tsh[s & 1];
        const float t1 = tsh[(s + 1) & 1];
        const float dt = t1 - t0;

        // stream prologue: 3 chunks in flight during layer 1
        issue_chunk(0, str_u32, W2, W3, tid);
        issue_chunk(1, str_u32, W2, W3, tid);
        issue_chunk(2, str_u32, W2, W3, tid);

        // ---- layer 1 (K=16, folded) ----
        {
            u64 acc[4] = { cig[0], cig[1], cig[2], cig[3] };
#pragma unroll
            for (int i = 0; i < 16; i++) {
                const float* hr = inp + i * 16 + gq8;
                ulonglong2 h01 = *(const ulonglong2*)(hr);
                ulonglong2 h23 = *(const ulonglong2*)(hr + 4);
                acc[0] = ffma2(h01.x, wxz[i], acc[0]);
                acc[1] = ffma2(h01.y, wxz[i], acc[1]);
                acc[2] = ffma2(h23.x, wxz[i], acc[2]);
                acc[3] = ffma2(h23.y, wxz[i], acc[3]);
            }
#pragma unroll
            for (int gp = 0; gp < 4; gp++) {
                float2 v = unpack2(acc[gp]);
                v.x = elu1(v.x); v.y = elu1(v.y);
                int g = gq * 4 + gp;
                *(u64*)(hA + j0 * 16 + g * 2)       = pack2(v.x, v.x);
                *(u64*)(hA + (j0 + 1) * 16 + g * 2) = pack2(v.y, v.y);
            }
        }
        __syncthreads();

        // t rolling slot: tsh[s&1] <- t[s+2]; prefetch t[s+3]
        if (tid == 192) {
            if (s + 2 < Tt) tsh[s & 1] = treg;
            if (s + 3 < Tt) treg = t[s + 3];
        }
        // z prefetch for step s+2
        float znext = 0.f;
        if (tid >= 64 && tid < 128 && s + 2 < Tt) znext = z[zbase + (size_t)(s + 2) * 8];

        // ---- layer 2 ----
        {
            u64 acc[4] = { bd2, bd2, bd2, bd2 };
            accum_rows(w2c, hA, 0, ICC, j0, gq8, acc);
#pragma unroll 1
            for (int k = 0; k < NCH; k++) {
                asm volatile("cp.async.wait_group 2;" ::: "memory");
                __syncthreads();
                issue_chunk(k + 3, str_u32, W2, W3, tid);
                accum_rows(strb + (k % NSTG) * STG_FLOATS, hA, ICC + k * CHROWS, CHROWS, j0, gq8, acc);
            }
#pragma unroll
            for (int gp = 0; gp < 4; gp++) {
                float2 v = unpack2(acc[gp]);
                v.x = elu1(v.x); v.y = elu1(v.y);
                int g = gq * 4 + gp;
                *(u64*)(hB + j0 * 16 + g * 2)       = pack2(v.x, v.x);
                *(u64*)(hB + (j0 + 1) * 16 + g * 2) = pack2(v.y, v.y);
            }
        }
        __syncthreads();

        // ---- layer 3 ----
        {
            u64 acc[4] = { bd3, bd3, bd3, bd3 };
            accum_rows(w3c, hB, 0, ICC, j0, gq8, acc);
#pragma unroll 1
            for (int c = 0; c < NCH; c++) {
                const int k = NCH + c;
                if (k < NKTOT - 2)       asm volatile("cp.async.wait_group 2;" ::: "memory");
                else if (k == NKTOT - 2) asm volatile("cp.async.wait_group 1;" ::: "memory");
                else                     asm volatile("cp.async.wait_group 0;" ::: "memory");
                __syncthreads();
                issue_chunk(k + 3, str_u32, W2, W3, tid);
                accum_rows(strb + (k % NSTG) * STG_FLOATS, hB, ICC + c * CHROWS, CHROWS, j0, gq8, acc);
            }
#pragma unroll
            for (int gp = 0; gp < 4; gp++) {
                float2 v = unpack2(acc[gp]);
                v.x = elu1(v.x); v.y = elu1(v.y);
                int g = gq * 4 + gp;
                *(float2*)(h3p + g * 260 + j0) = make_float2(v.x, v.y);
            }
        }
        __syncthreads();

        // ---- layer 4 partials ----
        {
            float p = 0.f;
            const int base = c4 * 64;
            const float* hp = h3p + g4 * 260 + base;
            const float* wp = w4t + k4 * 260 + base;
#pragma unroll
            for (int it = 0; it < 16; it++) {
                float4 hv = *(const float4*)(hp + it * 4);
                float4 wv = *(const float4*)(wp + it * 4);
                p = fmaf(hv.x, wv.x, p); p = fmaf(hv.y, wv.y, p);
                p = fmaf(hv.z, wv.z, p); p = fmaf(hv.w, wv.w, p);
            }
            red[tid] = p;
        }
        __syncthreads();

        // ---- epilogue ----
        if (tid < 64) {
            int k = tid & 7, g = tid >> 3;
            float o = b4s[k] + red[tid] + red[tid + 64] + red[tid + 128] + red[tid + 192];
            float xn = inp[k * 16 + g * 2] + dt * o;
            inp[k * 16 + g * 2] = xn; inp[k * 16 + g * 2 + 1] = xn;
            out[(size_t)(b0 + g) * Tt * 8 + (size_t)(s + 1) * 8 + k] = xn;
        } else if (tid < 128) {
            int r = tid - 64, g = r >> 3, zi = r & 7;
            float v = (t1 >= evts[g]) ? zjs[r] : zreg;
            inp[(8 + zi) * 16 + g * 2] = v; inp[(8 + zi) * 16 + g * 2 + 1] = v;
            zreg = znext;
        }
        __syncthreads();
    }
}

extern "C" void kernel_launch(void* const* d_in, const int* in_sizes, int n_in,
                              void* d_out, int out_size) {
    const float* t       = (const float*)d_in[0];
    const float* x       = (const float*)d_in[1];
    const float* z       = (const float*)d_in[2];
    const float* event_t = (const float*)d_in[3];
    const float* z_jump  = (const float*)d_in[4];
    const float* W1      = (const float*)d_in[5];
    const float* b1      = (const float*)d_in[6];
    const float* W2      = (const float*)d_in[7];
    const float* b2      = (const float*)d_in[8];
    const float* W3      = (const float*)d_in[9];
    const float* b3      = (const float*)d_in[10];
    const float* W4      = (const float*)d_in[11];
    const float* b4      = (const float*)d_in[12];
    float* out = (float*)d_out;

    cudaFuncSetAttribute(ode_main, cudaFuncAttributeMaxDynamicSharedMemorySize, SM_BYTES);

    ode_main<<<NBLK, NTHR, SM_BYTES>>>(t, x, z, event_t, z_jump,
                                       W1, b1, W2, b2, W3, b3, W4, b4, out);
}

// round 6
// speedup vs baseline: 1.5604x; 1.1491x over previous
#include <cuda_runtime.h>
#include <cstdint>

#define Bt    1024
#define Tt    1000
#define HH    256
#define NBLK  128
#define NTHR  256
#define ICC   64              // W2/W3 rows resident in SMEM (16 iterations of 4)
#define CHROWS 12             // rows per streamed chunk (3 iterations of 4)
#define NCH   16              // chunks per layer: (256-64)/12
#define NKTOT (2*NCH)         // 32
#define NSTG  4               // pipeline stages (issue 3 ahead, wait_group 2)

using u64 = unsigned long long;

__device__ __forceinline__ u64 ffma2(u64 a, u64 b, u64 c) {
    u64 d; asm("fma.rn.f32x2 %0,%1,%2,%3;" : "=l"(d) : "l"(a), "l"(b), "l"(c)); return d;
}
__device__ __forceinline__ u64 addf2(u64 a, u64 b) {
    u64 d; asm("add.rn.f32x2 %0,%1,%2;" : "=l"(d) : "l"(a), "l"(b)); return d;
}
__device__ __forceinline__ u64 pack2(float x, float y) {
    u64 d; asm("mov.b64 %0,{%1,%2};" : "=l"(d) : "f"(x), "f"(y)); return d;
}
__device__ __forceinline__ float2 unpack2(u64 a) {
    float2 f; asm("mov.b64 {%0,%1},%2;" : "=f"(f.x), "=f"(f.y) : "l"(a)); return f;
}
__device__ __forceinline__ float elu1(float v) { return v > 0.f ? v : (__expf(v) - 1.f); }

// ---------------- SMEM layout (float offsets) ----------------
#define OFF_W2   0                      // 64*256 = 16384
#define OFF_W3   16384                  // 16384
#define OFF_STR  32768                  // 4*12*256 = 12288
#define OFF_HA   45056                  // 256*16 = 4096 (dup)
#define OFF_HB   49152                  // 4096
#define OFF_H3   53248                  // 8*260 = 2080
#define OFF_W4   55328                  // 8*260 = 2080
#define OFF_INP  57408                  // 16*16 = 256 (dup)
#define OFF_RED  57664                  // 256 (also araw scratch)
#define OFF_ZJ   57920                  // 64
#define OFF_EVT  57984                  // 8
#define OFF_B4   57992                  // 8
#define OFF_TSH  58000                  // 2
#define SM_FLOATS 58004
#define SM_BYTES  (SM_FLOATS * 4)       // 232016 B  (< 232448 cap)

#define STG_FLOATS (CHROWS * HH)        // 3072

// one weight-row accumulation: acc{0,1}[g] += h[g] * (w pair)
__device__ __forceinline__ void accum_iter(const float* __restrict__ wrow_j0,
                                           const float* __restrict__ hrow,
                                           u64* __restrict__ acc0, u64* __restrict__ acc1) {
    ulonglong2 w = *(const ulonglong2*)wrow_j0;   // (w_j0,w_j1),(w_j2,w_j3)
    u64 hv[8];
    *(ulonglong2*)&hv[0] = *(const ulonglong2*)(hrow);
    *(ulonglong2*)&hv[2] = *(const ulonglong2*)(hrow + 4);
    *(ulonglong2*)&hv[4] = *(const ulonglong2*)(hrow + 8);
    *(ulonglong2*)&hv[6] = *(const ulonglong2*)(hrow + 12);
#pragma unroll
    for (int g = 0; g < 8; g++) {
        acc0[g] = ffma2(hv[g], w.x, acc0[g]);
        acc1[g] = ffma2(hv[g], w.y, acc1[g]);
    }
}

__device__ __forceinline__ void issue_chunk(int k, unsigned str_u32,
                                            const float* __restrict__ W2,
                                            const float* __restrict__ W3, int tid) {
    if (k >= NKTOT) return;
    const int kl = (k < NCH) ? k : (k - NCH);
    const char* src = (const char*)((k < NCH ? W2 : W3) + (ICC + kl * CHROWS) * HH);
    unsigned dst = str_u32 + (unsigned)(k % NSTG) * (STG_FLOATS * 4);
#pragma unroll
    for (int r = 0; r < 3; r++) {
        unsigned off = (unsigned)(tid + r * NTHR) * 16;
        asm volatile("cp.async.cg.shared.global [%0], [%1], 16;" :: "r"(dst + off), "l"(src + off));
    }
    asm volatile("cp.async.commit_group;");
}

// full 256->256 layer: K-quarter partials + shuffle reduction + bias + ELU + writeback
template <bool TO_H3P>
__device__ __forceinline__ void biglayerA(
    const float* __restrict__ wc, const float* __restrict__ strb,
    const float* __restrict__ W2, const float* __restrict__ W3,
    const float* __restrict__ hsrc, float* __restrict__ hdst,
    int j0, int kq, int ga, int layer, ulonglong2 bq,
    unsigned str_u32, int tid)
{
    u64 acc0[8], acc1[8];
#pragma unroll
    for (int g = 0; g < 8; g++) { acc0[g] = 0ull; acc1[g] = 0ull; }

    // cached rows: iterations n=0..15, this lane handles row 4n+kq
#pragma unroll 4
    for (int n = 0; n < ICC / 4; n++) {
        int i = n * 4 + kq;
        accum_iter(wc + i * HH + j0, hsrc + i * 16, acc0, acc1);
    }
    // streamed chunks
#pragma unroll 1
    for (int c = 0; c < NCH; c++) {
        const int k = layer * NCH + c;
        if (k < NKTOT - 2)       asm volatile("cp.async.wait_group 2;" ::: "memory");
        else if (k == NKTOT - 2) asm volatile("cp.async.wait_group 1;" ::: "memory");
        else                     asm volatile("cp.async.wait_group 0;" ::: "memory");
        __syncthreads();
        issue_chunk(k + 3, str_u32, W2, W3, tid);
        const float* sb = strb + (k % NSTG) * STG_FLOATS;
        const int base = ICC + c * CHROWS;
#pragma unroll
        for (int m = 0; m < 3; m++) {
            int io = m * 4 + kq;
            accum_iter(sb + io * HH + j0, hsrc + (base + io) * 16, acc0, acc1);
        }
    }

    // K-reduction across kq via shuffles (lanes ^8, ^16)
#pragma unroll
    for (int g = 0; g < 8; g++) {
        acc0[g] = addf2(acc0[g], __shfl_xor_sync(0xffffffffu, acc0[g], 8));
        acc0[g] = addf2(acc0[g], __shfl_xor_sync(0xffffffffu, acc0[g], 16));
        acc1[g] = addf2(acc1[g], __shfl_xor_sync(0xffffffffu, acc1[g], 8));
        acc1[g] = addf2(acc1[g], __shfl_xor_sync(0xffffffffu, acc1[g], 16));
    }

    // each lane finalizes its 2-batch slice (ga, ga+1) for j0..j0+3
    float2 bp  = unpack2(bq.x);   // bias (j0, j0+1)
    float2 bp2 = unpack2(bq.y);   // bias (j0+2, j0+3)
    float2 va = unpack2(acc0[ga]), vb = unpack2(acc0[ga + 1]);
    float a0 = elu1(va.x + bp.x),  a1 = elu1(vb.x + bp.x);    // j0   : g=ga, ga+1
    float c0 = elu1(va.y + bp.y),  c1 = elu1(vb.y + bp.y);    // j0+1
    float2 vc = unpack2(acc1[ga]), vd = unpack2(acc1[ga + 1]);
    float d0 = elu1(vc.x + bp2.x), d1 = elu1(vd.x + bp2.x);   // j0+2
    float e0 = elu1(vc.y + bp2.y), e1 = elu1(vd.y + bp2.y);   // j0+3

    if (TO_H3P) {
        *(float2*)(hdst + ga * 260 + j0)           = make_float2(a0, c0);
        *(float2*)(hdst + (ga + 1) * 260 + j0)     = make_float2(a1, c1);
        *(float2*)(hdst + ga * 260 + j0 + 2)       = make_float2(d0, e0);
        *(float2*)(hdst + (ga + 1) * 260 + j0 + 2) = make_float2(d1, e1);
    } else {
        *(float4*)(hdst + j0 * 16 + ga * 2)       = make_float4(a0, a0, a1, a1);
        *(float4*)(hdst + (j0 + 1) * 16 + ga * 2) = make_float4(c0, c0, c1, c1);
        *(float4*)(hdst + (j0 + 2) * 16 + ga * 2) = make_float4(d0, d0, d1, d1);
        *(float4*)(hdst + (j0 + 3) * 16 + ga * 2) = make_float4(e0, e0, e1, e1);
    }
}

__global__ __launch_bounds__(NTHR, 1)
void ode_main(const float* __restrict__ t, const float* __restrict__ x,
              const float* __restrict__ z, const float* __restrict__ event_t,
              const float* __restrict__ z_jump,
              const float* __restrict__ W1, const float* __restrict__ b1,
              const float* __restrict__ W2, const float* __restrict__ b2,
              const float* __restrict__ W3, const float* __restrict__ b3,
              const float* __restrict__ W4, const float* __restrict__ b4,
              float* __restrict__ out)
{
    extern __shared__ float sm[];
    float* w2c  = sm + OFF_W2;
    float* w3c  = sm + OFF_W3;
    float* strb = sm + OFF_STR;
    float* hA   = sm + OFF_HA;
    float* hB   = sm + OFF_HB;
    float* h3p  = sm + OFF_H3;
    float* w4t  = sm + OFF_W4;
    float* inp  = sm + OFF_INP;
    float* red  = sm + OFF_RED;
    float* zjs  = sm + OFF_ZJ;
    float* evts = sm + OFF_EVT;
    float* b4s  = sm + OFF_B4;
    float* tsh  = sm + OFF_TSH;

    const int tid = threadIdx.x;
    const int b0  = blockIdx.x * 8;
    const unsigned str_u32 = (unsigned)__cvta_generic_to_shared(strb);

    // ---- lane decompositions ----
    const int lane = tid & 31, warp = tid >> 5;
    // big layers: j-quad x 8 batches x K-quarter
    const int quad = warp * 8 + (lane & 7);
    const int j0q  = quad * 4;
    const int kq   = lane >> 3;
    const int ga   = kq * 2;
    // layer 1: j-pair x 4 batches
    const int j0  = warp * 32 + (lane & 15) * 2;
    const int gq  = lane >> 4;
    const int gq8 = gq * 8;

    // ---- init: SMEM caches + raw inputs ----
    for (int idx = tid; idx < ICC * HH; idx += NTHR) { w2c[idx] = W2[idx]; w3c[idx] = W3[idx]; }
    for (int idx = tid; idx < 8 * HH; idx += NTHR) {
        int k = idx >> 8, i = idx & 255;
        w4t[k * 260 + i] = W4[i * 8 + k];
    }
    if (tid < 8) { evts[tid] = event_t[b0 + tid]; b4s[tid] = b4[tid]; }
    if (tid < 64) { int g = tid >> 3, i = tid & 7; zjs[tid] = z_jump[(b0 + g) * 8 + i]; }
    if (tid == 0) { tsh[0] = t[0]; tsh[1] = t[1]; }

    float zreg = 0.f; size_t zbase = 0;
    if (tid >= 64 && tid < 128) {
        int r = tid - 64, g = r >> 3, i = r & 7;
        zbase = (size_t)(b0 + g) * Tt * 8 + i;
    }
    float treg = 0.f;
    if (tid == 192) treg = t[2];

    if (tid < 64) {
        int k = tid & 7, g = tid >> 3;
        float xv = x[(size_t)(b0 + g) * Tt * 8 + k];
        red[k * 8 + g] = xv;
        inp[k * 16 + g * 2] = xv; inp[k * 16 + g * 2 + 1] = xv;
        out[(size_t)(b0 + g) * Tt * 8 + k] = xv;
    } else if (tid < 128) {
        int r = tid - 64, g = r >> 3, zi = r & 7;
        float z0 = z[zbase];
        red[(8 + zi) * 8 + g] = z0;
        zreg = z[zbase + 8];
    }
    __syncthreads();

    if (tid >= 64 && tid < 128) {
        int r = tid - 64, g = r >> 3, zi = r & 7;
        float v = (tsh[0] >= evts[g]) ? zjs[r] : red[(8 + zi) * 8 + g];
        inp[(8 + zi) * 16 + g * 2] = v; inp[(8 + zi) * 16 + g * 2 + 1] = v;
    }

    // per-thread layer-1 weights + cinit
    u64 wxz[16];
    u64 cig[4];
    {
        float c0 = b1[j0], c1 = b1[j0 + 1];
        float ca[4][2];
#pragma unroll
        for (int gp = 0; gp < 4; gp++) { ca[gp][0] = c0; ca[gp][1] = c1; }
#pragma unroll
        for (int i = 0; i < 16; i++) {
            float2 wa = *(const float2*)&W1[i * HH + j0];
            float2 wb = *(const float2*)&W1[(16 + i) * HH + j0];
            float2 wc = *(const float2*)&W1[(32 + i) * HH + j0];
            wxz[i] = pack2(wb.x + wc.x, wb.y + wc.y);
            float dx = wa.x - wb.x, dy = wa.y - wb.y;
#pragma unroll
            for (int gp = 0; gp < 4; gp++) {
                float a = red[i * 8 + gq * 4 + gp];
                ca[gp][0] = fmaf(a, dx, ca[gp][0]);
                ca[gp][1] = fmaf(a, dy, ca[gp][1]);
            }
        }
#pragma unroll
        for (int gp = 0; gp < 4; gp++) cig[gp] = pack2(ca[gp][0], ca[gp][1]);
    }
    const ulonglong2 b2q = *(const ulonglong2*)&b2[j0q];
    const ulonglong2 b3q = *(const ulonglong2*)&b3[j0q];

    const int c4 = tid >> 6, r4 = tid & 63, k4 = r4 & 7, g4 = r4 >> 3;
    __syncthreads();

    for (int s = 0; s < Tt - 1; s++) {
        const float t0 = tsh[s & 1];
        const float t1 = tsh[(s + 1) & 1];
        const float dt = t1 - t0;

        // stream prologue: 3 chunks in flight during layer 1
        issue_chunk(0, str_u32, W2, W3, tid);
        issue_chunk(1, str_u32, W2, W3, tid);
        issue_chunk(2, str_u32, W2, W3, tid);

        // ---- layer 1 (K=16, folded) ----
        {
            u64 acc[4] = { cig[0], cig[1], cig[2], cig[3] };
#pragma unroll
            for (int i = 0; i < 16; i++) {
                const float* hr = inp + i * 16 + gq8;
                ulonglong2 h01 = *(const ulonglong2*)(hr);
                ulonglong2 h23 = *(const ulonglong2*)(hr + 4);
                acc[0] = ffma2(h01.x, wxz[i], acc[0]);
                acc[1] = ffma2(h01.y, wxz[i], acc[1]);
                acc[2] = ffma2(h23.x, wxz[i], acc[2]);
                acc[3] = ffma2(h23.y, wxz[i], acc[3]);
            }
#pragma unroll
            for (int gp = 0; gp < 4; gp++) {
                float2 v = unpack2(acc[gp]);
                v.x = elu1(v.x); v.y = elu1(v.y);
                int g = gq * 4 + gp;
                *(u64*)(hA + j0 * 16 + g * 2)       = pack2(v.x, v.x);
                *(u64*)(hA + (j0 + 1) * 16 + g * 2) = pack2(v.y, v.y);
            }
        }
        __syncthreads();

        // t rolling slot + z prefetch for step s+2
        if (tid == 192) {
            if (s + 2 < Tt) tsh[s & 1] = treg;
            if (s + 3 < Tt) treg = t[s + 3];
        }
        float znext = 0.f;
        if (tid >= 64 && tid < 128 && s + 2 < Tt) znext = z[zbase + (size_t)(s + 2) * 8];

        // ---- layer 2 ----
        biglayerA<false>(w2c, strb, W2, W3, hA, hB, j0q, kq, ga, 0, b2q, str_u32, tid);
        __syncthreads();

        // ---- layer 3 ----
        biglayerA<true>(w3c, strb, W2, W3, hB, h3p, j0q, kq, ga, 1, b3q, str_u32, tid);
        __syncthreads();

        // ---- layer 4 partials ----
        {
            float p = 0.f;
            const int base = c4 * 64;
            const float* hp = h3p + g4 * 260 + base;
            const float* wp = w4t + k4 * 260 + base;
#pragma unroll
            for (int it = 0; it < 16; it++) {
                float4 hv = *(const float4*)(hp + it * 4);
                float4 wv = *(const float4*)(wp + it * 4);
                p = fmaf(hv.x, wv.x, p); p = fmaf(hv.y, wv.y, p);
                p = fmaf(hv.z, wv.z, p); p = fmaf(hv.w, wv.w, p);
            }
            red[tid] = p;
        }
        __syncthreads();

        // ---- epilogue ----
        if (tid < 64) {
            int k = tid & 7, g = tid >> 3;
            float o = b4s[k] + red[tid] + red[tid + 64] + red[tid + 128] + red[tid + 192];
            float xn = inp[k * 16 + g * 2] + dt * o;
            inp[k * 16 + g * 2] = xn; inp[k * 16 + g * 2 + 1] = xn;
            out[(size_t)(b0 + g) * Tt * 8 + (size_t)(s + 1) * 8 + k] = xn;
        } else if (tid < 128) {
            int r = tid - 64, g = r >> 3, zi = r & 7;
            float v = (t1 >= evts[g]) ? zjs[r] : zreg;
            inp[(8 + zi) * 16 + g * 2] = v; inp[(8 + zi) * 16 + g * 2 + 1] = v;
            zreg = znext;
        }
        __syncthreads();
    }
}

extern "C" void kernel_launch(void* const* d_in, const int* in_sizes, int n_in,
                              void* d_out, int out_size) {
    const float* t       = (const float*)d_in[0];
    const float* x       = (const float*)d_in[1];
    const float* z       = (const float*)d_in[2];
    const float* event_t = (const float*)d_in[3];
    const float* z_jump  = (const float*)d_in[4];
    const float* W1      = (const float*)d_in[5];
    const float* b1      = (const float*)d_in[6];
    const float* W2      = (const float*)d_in[7];
    const float* b2      = (const float*)d_in[8];
    const float* W3      = (const float*)d_in[9];
    const float* b3      = (const float*)d_in[10];
    const float* W4      = (const float*)d_in[11];
    const float* b4      = (const float*)d_in[12];
    float* out = (float*)d_out;

    cudaFuncSetAttribute(ode_main, cudaFuncAttributeMaxDynamicSharedMemorySize, SM_BYTES);

    ode_main<<<NBLK, NTHR, SM_BYTES>>>(t, x, z, event_t, z_jump,
                                       W1, b1, W2, b2, W3, b3, W4, b4, out);
}

// round 7
// speedup vs baseline: 1.7578x; 1.1265x over previous
#include <cuda_runtime.h>
#include <cstdint>

#define Bt    1024
#define Tt    1000
#define HH    256
#define NBLK  128
#define NTHR  256
#define ICC   48              // W2/W3 rows resident in SMEM (12 iterations of 4)
#define CHROWS 16             // rows per streamed chunk (4 iterations of 4)
#define NCH   13              // chunks per layer: (256-48)/16
#define NKTOT (2*NCH)         // 26
#define NSTG  4               // pipeline stages (issue 3 ahead, wait_group 2)
#define HSTR  20              // dup-activation row stride (16 data + 4 pad) -> conflict-free

using u64 = unsigned long long;

__device__ __forceinline__ u64 ffma2(u64 a, u64 b, u64 c) {
    u64 d; asm("fma.rn.f32x2 %0,%1,%2,%3;" : "=l"(d) : "l"(a), "l"(b), "l"(c)); return d;
}
__device__ __forceinline__ u64 addf2(u64 a, u64 b) {
    u64 d; asm("add.rn.f32x2 %0,%1,%2;" : "=l"(d) : "l"(a), "l"(b)); return d;
}
__device__ __forceinline__ u64 pack2(float x, float y) {
    u64 d; asm("mov.b64 %0,{%1,%2};" : "=l"(d) : "f"(x), "f"(y)); return d;
}
__device__ __forceinline__ float2 unpack2(u64 a) {
    float2 f; asm("mov.b64 {%0,%1},%2;" : "=f"(f.x), "=f"(f.y) : "l"(a)); return f;
}
__device__ __forceinline__ float elu1(float v) { return v > 0.f ? v : (__expf(v) - 1.f); }

// ---------------- SMEM layout (float offsets) ----------------
#define OFF_W2   0                      // 48*256 = 12288
#define OFF_W3   12288                  // 12288
#define OFF_STR  24576                  // 4*16*256 = 16384
#define OFF_HA   40960                  // 256*20 = 5120 (dup, padded)
#define OFF_HB   46080                  // 5120
#define OFF_H3   51200                  // 8*260 = 2080
#define OFF_W4   53280                  // 8*260 = 2080
#define OFF_INP  55360                  // 16*16 = 256 (dup, stride 16)
#define OFF_RED  55616                  // 256 (also araw scratch)
#define OFF_ZJ   55872                  // 64
#define OFF_EVT  55936                  // 8
#define OFF_B4   55944                  // 8
#define OFF_TSH  55952                  // 2
#define SM_FLOATS 55954
#define SM_BYTES  (SM_FLOATS * 4)       // 223816 B (< 232448 cap)

#define STG_FLOATS (CHROWS * HH)        // 4096

// one weight-row accumulation: acc{0,1}[g] += h[g] * (w pair); h rows stride HSTR
__device__ __forceinline__ void accum_iter(const float* __restrict__ wrow_j0,
                                           const float* __restrict__ hrow,
                                           u64* __restrict__ acc0, u64* __restrict__ acc1) {
    ulonglong2 w = *(const ulonglong2*)wrow_j0;   // (w_j0,w_j1),(w_j2,w_j3)
    u64 hv[8];
    *(ulonglong2*)&hv[0] = *(const ulonglong2*)(hrow);
    *(ulonglong2*)&hv[2] = *(const ulonglong2*)(hrow + 4);
    *(ulonglong2*)&hv[4] = *(const ulonglong2*)(hrow + 8);
    *(ulonglong2*)&hv[6] = *(const ulonglong2*)(hrow + 12);
#pragma unroll
    for (int g = 0; g < 8; g++) {
        acc0[g] = ffma2(hv[g], w.x, acc0[g]);
        acc1[g] = ffma2(hv[g], w.y, acc1[g]);
    }
}

__device__ __forceinline__ void issue_chunk(int k, unsigned str_u32,
                                            const float* __restrict__ W2,
                                            const float* __restrict__ W3, int tid) {
    if (k >= NKTOT) return;
    const int kl = (k < NCH) ? k : (k - NCH);
    const char* src = (const char*)((k < NCH ? W2 : W3) + (ICC + kl * CHROWS) * HH);
    unsigned dst = str_u32 + (unsigned)(k % NSTG) * (STG_FLOATS * 4);
#pragma unroll
    for (int r = 0; r < 4; r++) {
        unsigned off = (unsigned)(tid + r * NTHR) * 16;
        asm volatile("cp.async.cg.shared.global [%0], [%1], 16;" :: "r"(dst + off), "l"(src + off));
    }
    asm volatile("cp.async.commit_group;");
}

// full 256->256 layer: K-quarter partials + shuffle reduction + bias + ELU + writeback
template <bool TO_H3P>
__device__ __forceinline__ void biglayerA(
    const float* __restrict__ wc, const float* __restrict__ strb,
    const float* __restrict__ W2, const float* __restrict__ W3,
    const float* __restrict__ hsrc, float* __restrict__ hdst,
    int j0, int kq, int ga, int layer, ulonglong2 bq,
    unsigned str_u32, int tid)
{
    u64 acc0[8], acc1[8];
#pragma unroll
    for (int g = 0; g < 8; g++) { acc0[g] = 0ull; acc1[g] = 0ull; }

    // cached rows: iterations n, this lane handles row 4n+kq
#pragma unroll 4
    for (int n = 0; n < ICC / 4; n++) {
        int i = n * 4 + kq;
        accum_iter(wc + i * HH + j0, hsrc + i * HSTR, acc0, acc1);
    }
    // streamed chunks
#pragma unroll 1
    for (int c = 0; c < NCH; c++) {
        const int k = layer * NCH + c;
        if (k < NKTOT - 2)       asm volatile("cp.async.wait_group 2;" ::: "memory");
        else if (k == NKTOT - 2) asm volatile("cp.async.wait_group 1;" ::: "memory");
        else                     asm volatile("cp.async.wait_group 0;" ::: "memory");
        __syncthreads();
        issue_chunk(k + 3, str_u32, W2, W3, tid);
        const float* sb = strb + (k % NSTG) * STG_FLOATS;
        const int base = ICC + c * CHROWS;
#pragma unroll
        for (int m = 0; m < 4; m++) {
            int io = m * 4 + kq;
            accum_iter(sb + io * HH + j0, hsrc + (base + io) * HSTR, acc0, acc1);
        }
    }

    // K-reduction across kq via shuffles (lanes ^8, ^16)
#pragma unroll
    for (int g = 0; g < 8; g++) {
        acc0[g] = addf2(acc0[g], __shfl_xor_sync(0xffffffffu, acc0[g], 8));
        acc0[g] = addf2(acc0[g], __shfl_xor_sync(0xffffffffu, acc0[g], 16));
        acc1[g] = addf2(acc1[g], __shfl_xor_sync(0xffffffffu, acc1[g], 8));
        acc1[g] = addf2(acc1[g], __shfl_xor_sync(0xffffffffu, acc1[g], 16));
    }

    // each lane finalizes its 2-batch slice (ga, ga+1) for j0..j0+3
    float2 bp  = unpack2(bq.x);   // bias (j0, j0+1)
    float2 bp2 = unpack2(bq.y);   // bias (j0+2, j0+3)
    float2 va = unpack2(acc0[ga]), vb = unpack2(acc0[ga + 1]);
    float a0 = elu1(va.x + bp.x),  a1 = elu1(vb.x + bp.x);    // j0   : g=ga, ga+1
    float c0 = elu1(va.y + bp.y),  c1 = elu1(vb.y + bp.y);    // j0+1
    float2 vc = unpack2(acc1[ga]), vd = unpack2(acc1[ga + 1]);
    float d0 = elu1(vc.x + bp2.x), d1 = elu1(vd.x + bp2.x);   // j0+2
    float e0 = elu1(vc.y + bp2.y), e1 = elu1(vd.y + bp2.y);   // j0+3

    if (TO_H3P) {
        *(float2*)(hdst + ga * 260 + j0)           = make_float2(a0, c0);
        *(float2*)(hdst + (ga + 1) * 260 + j0)     = make_float2(a1, c1);
        *(float2*)(hdst + ga * 260 + j0 + 2)       = make_float2(d0, e0);
        *(float2*)(hdst + (ga + 1) * 260 + j0 + 2) = make_float2(d1, e1);
    } else {
        *(float4*)(hdst + j0 * HSTR + ga * 2)       = make_float4(a0, a0, a1, a1);
        *(float4*)(hdst + (j0 + 1) * HSTR + ga * 2) = make_float4(c0, c0, c1, c1);
        *(float4*)(hdst + (j0 + 2) * HSTR + ga * 2) = make_float4(d0, d0, d1, d1);
        *(float4*)(hdst + (j0 + 3) * HSTR + ga * 2) = make_float4(e0, e0, e1, e1);
    }
}

__global__ __launch_bounds__(NTHR, 1)
void ode_main(const float* __restrict__ t, const float* __restrict__ x,
              const float* __restrict__ z, const float* __restrict__ event_t,
              const float* __restrict__ z_jump,
              const float* __restrict__ W1, const float* __restrict__ b1,
              const float* __restrict__ W2, const float* __restrict__ b2,
              const float* __restrict__ W3, const float* __restrict__ b3,
              const float* __restrict__ W4, const float* __restrict__ b4,
              float* __restrict__ out)
{
    extern __shared__ float sm[];
    float* w2c  = sm + OFF_W2;
    float* w3c  = sm + OFF_W3;
    float* strb = sm + OFF_STR;
    float* hA   = sm + OFF_HA;
    float* hB   = sm + OFF_HB;
    float* h3p  = sm + OFF_H3;
    float* w4t  = sm + OFF_W4;
    float* inp  = sm + OFF_INP;
    float* red  = sm + OFF_RED;
    float* zjs  = sm + OFF_ZJ;
    float* evts = sm + OFF_EVT;
    float* b4s  = sm + OFF_B4;
    float* tsh  = sm + OFF_TSH;

    const int tid = threadIdx.x;
    const int b0  = blockIdx.x * 8;
    const unsigned str_u32 = (unsigned)__cvta_generic_to_shared(strb);

    // ---- lane decompositions ----
    const int lane = tid & 31, warp = tid >> 5;
    // big layers: j-quad x 8 batches x K-quarter
    const int quad = warp * 8 + (lane & 7);
    const int j0q  = quad * 4;
    const int kq   = lane >> 3;
    const int ga   = kq * 2;
    // layer 1: j-pair x 4 batches
    const int j0  = warp * 32 + (lane & 15) * 2;
    const int gq  = lane >> 4;
    const int gq8 = gq * 8;

    // ---- init: SMEM caches + raw inputs ----
    for (int idx = tid; idx < ICC * HH; idx += NTHR) { w2c[idx] = W2[idx]; w3c[idx] = W3[idx]; }
    for (int idx = tid; idx < 8 * HH; idx += NTHR) {
        int k = idx >> 8, i = idx & 255;
        w4t[k * 260 + i] = W4[i * 8 + k];
    }
    if (tid < 8) { evts[tid] = event_t[b0 + tid]; b4s[tid] = b4[tid]; }
    if (tid < 64) { int g = tid >> 3, i = tid & 7; zjs[tid] = z_jump[(b0 + g) * 8 + i]; }
    if (tid == 0) { tsh[0] = t[0]; tsh[1] = t[1]; }

    float zreg = 0.f; size_t zbase = 0;
    if (tid >= 64 && tid < 128) {
        int r = tid - 64, g = r >> 3, i = r & 7;
        zbase = (size_t)(b0 + g) * Tt * 8 + i;
    }
    float treg = 0.f;
    if (tid == 192) treg = t[2];

    if (tid < 64) {
        int k = tid & 7, g = tid >> 3;
        float xv = x[(size_t)(b0 + g) * Tt * 8 + k];
        red[k * 8 + g] = xv;
        inp[k * 16 + g * 2] = xv; inp[k * 16 + g * 2 + 1] = xv;
        out[(size_t)(b0 + g) * Tt * 8 + k] = xv;
    } else if (tid < 128) {
        int r = tid - 64, g = r >> 3, zi = r & 7;
        float z0 = z[zbase];
        red[(8 + zi) * 8 + g] = z0;
        zreg = z[zbase + 8];
    }
    __syncthreads();

    if (tid >= 64 && tid < 128) {
        int r = tid - 64, g = r >> 3, zi = r & 7;
        float v = (tsh[0] >= evts[g]) ? zjs[r] : red[(8 + zi) * 8 + g];
        inp[(8 + zi) * 16 + g * 2] = v; inp[(8 + zi) * 16 + g * 2 + 1] = v;
    }

    // per-thread layer-1 weights + cinit
    u64 wxz[16];
    u64 cig[4];
    {
        float c0 = b1[j0], c1 = b1[j0 + 1];
        float ca[4][2];
#pragma unroll
        for (int gp = 0; gp < 4; gp++) { ca[gp][0] = c0; ca[gp][1] = c1; }
#pragma unroll
        for (int i = 0; i < 16; i++) {
            float2 wa = *(const float2*)&W1[i * HH + j0];
            float2 wb = *(const float2*)&W1[(16 + i) * HH + j0];
            float2 wc = *(const float2*)&W1[(32 + i) * HH + j0];
            wxz[i] = pack2(wb.x + wc.x, wb.y + wc.y);
            float dx = wa.x - wb.x, dy = wa.y - wb.y;
#pragma unroll
            for (int gp = 0; gp < 4; gp++) {
                float a = red[i * 8 + gq * 4 + gp];
                ca[gp][0] = fmaf(a, dx, ca[gp][0]);
                ca[gp][1] = fmaf(a, dy, ca[gp][1]);
            }
        }
#pragma unroll
        for (int gp = 0; gp < 4; gp++) cig[gp] = pack2(ca[gp][0], ca[gp][1]);
    }
    const ulonglong2 b2q = *(const ulonglong2*)&b2[j0q];
    const ulonglong2 b3q = *(const ulonglong2*)&b3[j0q];

    const int c4 = tid >> 6, r4 = tid & 63, k4 = r4 & 7, g4 = r4 >> 3;
    __syncthreads();

    for (int s = 0; s < Tt - 1; s++) {
        const float t0 = tsh[s & 1];
        const float t1 = tsh[(s + 1) & 1];
        const float dt = t1 - t0;

        // stream prologue: 3 chunks in flight during layer 1
        issue_chunk(0, str_u32, W2, W3, tid);
        issue_chunk(1, str_u32, W2, W3, tid);
        issue_chunk(2, str_u32, W2, W3, tid);

        // ---- layer 1 (K=16, folded) ----
        {
            u64 acc[4] = { cig[0], cig[1], cig[2], cig[3] };
#pragma unroll
            for (int i = 0; i < 16; i++) {
                const float* hr = inp + i * 16 + gq8;
                ulonglong2 h01 = *(const ulonglong2*)(hr);
                ulonglong2 h23 = *(const ulonglong2*)(hr + 4);
                acc[0] = ffma2(h01.x, wxz[i], acc[0]);
                acc[1] = ffma2(h01.y, wxz[i], acc[1]);
                acc[2] = ffma2(h23.x, wxz[i], acc[2]);
                acc[3] = ffma2(h23.y, wxz[i], acc[3]);
            }
#pragma unroll
            for (int gp = 0; gp < 4; gp++) {
                float2 v = unpack2(acc[gp]);
                v.x = elu1(v.x); v.y = elu1(v.y);
                int g = gq * 4 + gp;
                *(u64*)(hA + j0 * HSTR + g * 2)       = pack2(v.x, v.x);
                *(u64*)(hA + (j0 + 1) * HSTR + g * 2) = pack2(v.y, v.y);
            }
        }
        __syncthreads();

        // t rolling slot + z prefetch for step s+2
        if (tid == 192) {
            if (s + 2 < Tt) tsh[s & 1] = treg;
            if (s + 3 < Tt) treg = t[s + 3];
        }
        float znext = 0.f;
        if (tid >= 64 && tid < 128 && s + 2 < Tt) znext = z[zbase + (size_t)(s + 2) * 8];

        // ---- layer 2 ----
        biglayerA<false>(w2c, strb, W2, W3, hA, hB, j0q, kq, ga, 0, b2q, str_u32, tid);
        __syncthreads();

        // ---- layer 3 ----
        biglayerA<true>(w3c, strb, W2, W3, hB, h3p, j0q, kq, ga, 1, b3q, str_u32, tid);
        __syncthreads();

        // ---- layer 4 partials ----
        {
            float p = 0.f;
            const int base = c4 * 64;
            const float* hp = h3p + g4 * 260 + base;
            const float* wp = w4t + k4 * 260 + base;
#pragma unroll
            for (int it = 0; it < 16; it++) {
                float4 hv = *(const float4*)(hp + it * 4);
                float4 wv = *(const float4*)(wp + it * 4);
                p = fmaf(hv.x, wv.x, p); p = fmaf(hv.y, wv.y, p);
                p = fmaf(hv.z, wv.z, p); p = fmaf(hv.w, wv.w, p);
            }
            red[tid] = p;
        }
        __syncthreads();

        // ---- epilogue ----
        if (tid < 64) {
            int k = tid & 7, g = tid >> 3;
            float o = b4s[k] + red[tid] + red[tid + 64] + red[tid + 128] + red[tid + 192];
            float xn = inp[k * 16 + g * 2] + dt * o;
            inp[k * 16 + g * 2] = xn; inp[k * 16 + g * 2 + 1] = xn;
            out[(size_t)(b0 + g) * Tt * 8 + (size_t)(s + 1) * 8 + k] = xn;
        } else if (tid < 128) {
            int r = tid - 64, g = r >> 3, zi = r & 7;
            float v = (t1 >= evts[g]) ? zjs[r] : zreg;
            inp[(8 + zi) * 16 + g * 2] = v; inp[(8 + zi) * 16 + g * 2 + 1] = v;
            zreg = znext;
        }
        __syncthreads();
    }
}

extern "C" void kernel_launch(void* const* d_in, const int* in_sizes, int n_in,
                              void* d_out, int out_size) {
    const float* t       = (const float*)d_in[0];
    const float* x       = (const float*)d_in[1];
    const float* z       = (const float*)d_in[2];
    const float* event_t = (const float*)d_in[3];
    const float* z_jump  = (const float*)d_in[4];
    const float* W1      = (const float*)d_in[5];
    const float* b1      = (const float*)d_in[6];
    const float* W2      = (const float*)d_in[7];
    const float* b2      = (const float*)d_in[8];
    const float* W3      = (const float*)d_in[9];
    const float* b3      = (const float*)d_in[10];
    const float* W4      = (const float*)d_in[11];
    const float* b4      = (const float*)d_in[12];
    float* out = (float*)d_out;

    cudaFuncSetAttribute(ode_main, cudaFuncAttributeMaxDynamicSharedMemorySize, SM_BYTES);

    ode_main<<<NBLK, NTHR, SM_BYTES>>>(t, x, z, event_t, z_jump,
                                       W1, b1, W2, b2, W3, b3, W4, b4, out);
}